// round 7
// baseline (speedup 1.0000x reference)
#include <cuda_runtime.h>

#define N_    256
#define H_    450
#define LAT_  56
#define V_    780
#define L_    511
#define NLAB_ 256
#define WZLD  (V_ + H_)

#define NB 29          // persistent blocks
#define NT 512         // threads per block (16 warps)
#define NW (NT / 32)

#define O_PSTOP 511
#define O_RLAB  1022
#define O_PLAB  1278

// ---------------- static device scratch (padded +64 for fixed-stride matvec loads) ----------------
__device__ float g_Sact[N_ * H_];          // running column sums
__device__ float g_hedge[L_ * H_ + 64];    // h written at step t (edge a_t -> b_t)
__device__ float g_uh[L_ * H_ + 64];       // uh[t*H+h] = Ur_h . h_edge[t]
__device__ float g_snap[L_ * H_];          // Sact[a_t] snapshot for d3 GEMM
__device__ float g_sbuf[512];              // per-step s vector (padded)
__device__ float g_rbuf[512];              // per-step rsum vector (padded)
__device__ float g_zpre[N_ * H_];
__device__ float g_wpre[N_ * H_];
__device__ float g_r1[N_ * H_];
__device__ float g_c1[N_];
__device__ float g_wllat[H_];              // Wl[:, :LAT]@latent + Wl_b
__device__ int   g_alist[L_ * 512];        // active in-edge steps (includes t-1, excludes sub)
__device__ int   g_acnt[L_];
__device__ int   g_asub[L_];
__device__ volatile int g_flags[32];

__device__ __forceinline__ float sigf(float x) { return 1.0f / (1.0f + __expf(-x)); }

__device__ __forceinline__ float warpsum(float v) {
#pragma unroll
    for (int o = 16; o; o >>= 1) v += __shfl_xor_sync(0xffffffffu, v, o);
    return v;
}

// ---------------- setup: zero running state + flags ----------------
__global__ void k_zero() {
    int i = blockIdx.x * blockDim.x + threadIdx.x;
    int stride = gridDim.x * blockDim.x;
    for (; i < N_ * H_; i += stride) g_Sact[i] = 0.f;
    if (blockIdx.x == 0 && threadIdx.x < 32) g_flags[threadIdx.x] = 0;
}

// ---------------- setup: per-node precompute tables (R1-identical) ----------------
__global__ __launch_bounds__(256) void k_tables(
    const float* __restrict__ nf, const float* __restrict__ latent,
    const float* __restrict__ Wz_w, const float* __restrict__ Wz_b,
    const float* __restrict__ Wr_w, const float* __restrict__ Wr_b,
    const float* __restrict__ Wh_w, const float* __restrict__ Wh_b,
    const float* __restrict__ Wd12_w, const float* __restrict__ Wd12_b,
    const float* __restrict__ Ud_w,
    const float* __restrict__ Wl_w, const float* __restrict__ Wl_b) {
    __shared__ int   s_vid;
    __shared__ float s_red[256];
    int n = blockIdx.x, tid = threadIdx.x;
    if (tid == 0) s_vid = 0;
    __syncthreads();
    for (int j = tid; j < V_; j += 256)
        if (nf[(size_t)n * V_ + j] > 0.5f) s_vid = j;   // one-hot: exactly one writer
    __syncthreads();
    int v = s_vid;

    float part = 0.f;
    for (int h = tid; h < H_; h += 256) {
        g_zpre[n * H_ + h] = Wz_w[(size_t)h * WZLD + v] + Wz_b[h];
        g_wpre[n * H_ + h] = Wh_w[(size_t)h * WZLD + v] + Wh_b[h];
        g_r1[n * H_ + h]   = Wr_w[(size_t)h * V_ + v] + Wr_b[h];
        float d = Wd12_w[(size_t)h * (V_ + LAT_) + v] + Wd12_b[h];
        for (int l = 0; l < LAT_; l++)
            d += Wd12_w[(size_t)h * (V_ + LAT_) + V_ + l] * latent[l];
        part += Ud_w[h] * fmaxf(d, 0.f);
    }
    s_red[tid] = part;
    __syncthreads();
    for (int s = 128; s; s >>= 1) { if (tid < s) s_red[tid] += s_red[tid + s]; __syncthreads(); }
    if (tid == 0) g_c1[n] = s_red[0];

    if (n == 0) {
        for (int h = tid; h < H_; h += 256) {
            float w = Wl_b[h];
            for (int l = 0; l < LAT_; l++)
                w += Wl_w[(size_t)h * (H_ + LAT_) + l] * latent[l];
            g_wllat[h] = w;
        }
    }
}

// ---------------- setup: active-edge lists (R1-identical semantics; alist includes t-1) ----------------
__global__ void k_path(const int* __restrict__ a_, const int* __restrict__ b_) {
    int t = blockIdx.x * blockDim.x + threadIdx.x;
    if (t >= L_) return;
    int a = a_[t], b = b_[t];
    int cnt = 0, sub = -1;
    for (int tw = 0; tw < t; tw++) {      // steps tw<t all write edge (a_tw -> b_tw)
        if (b_[tw] == a) {
            if (a_[tw] == b) sub = tw;    // the removed edge (b->a)
            else g_alist[t * 512 + cnt++] = tw;
        }
    }
    g_acnt[t] = cnt;
    g_asub[t] = sub;
}

// ---------------- flag-based grid barrier (fence-before-signal, R1-equivalent visibility) ----------------
__device__ __forceinline__ void gridbar(int gen) {
    __threadfence();                       // every thread drains its own prior stores
    __syncthreads();
    if (threadIdx.x < 32) {
        if (threadIdx.x == 0) g_flags[blockIdx.x] = gen;
        bool done = threadIdx.x >= NB;
        while (!__all_sync(0xffffffffu, done))
            if (!done) done = g_flags[threadIdx.x] >= gen;
    }
    __syncthreads();
}

// ---------------- the sequential recurrence (R1 dataflow + register weights + parallel rsum) ----------------
__global__ void __launch_bounds__(NT, 1) k_seq(
    const int* __restrict__ node_ids, const int* __restrict__ next_ids,
    const float* __restrict__ Wz_w, const float* __restrict__ Wh_w,
    const float* __restrict__ Ur_w) {
    int tid = threadIdx.x, lane = tid & 31, wid = tid >> 5;
    int h = blockIdx.x * NW + wid;            // 0..463
    bool act = h < H_;
    int hc = act ? h : H_ - 1;

    // weight rows in registers (zero-padded beyond H_)
    float ur[15], wz[15], wh[15];
#pragma unroll
    for (int s = 0; s < 15; s++) {
        int k = s * 32 + lane;
        bool ok = act && k < H_;
        ur[s] = ok ? Ur_w[(size_t)h * H_ + k] : 0.f;
        wz[s] = ok ? Wz_w[(size_t)h * WZLD + V_ + k] : 0.f;
        wh[s] = ok ? Wh_w[(size_t)h * WZLD + V_ + k] : 0.f;
    }

    int gen = 0;
    for (int t = 0; t < L_; t++) {
        int a   = __ldg(&node_ids[t]);
        int bn  = __ldg(&next_ids[t]);
        int sub = __ldg(&g_asub[t]);
        int cnt = __ldg(&g_acnt[t]);

        // ---- Phase A: uh for newest edge, s, rsum ----
        float r1v = __ldg(&g_r1[a * H_ + hc]);
        float uhv = 0.f;
        if (t > 0) {
            const float* hp = &g_hedge[(size_t)(t - 1) * H_];
            float acc = 0.f;
#pragma unroll
            for (int s = 0; s < 15; s++) acc += ur[s] * __ldcg(&hp[s * 32 + lane]);
            uhv = warpsum(acc);
            if (act && lane == 0) g_uh[(size_t)(t - 1) * H_ + h] = uhv;
        }
        // lane-parallel rsum over alist (alist includes t-1; uhv is warp-uniform)
        float part = 0.f;
        for (int base = 0; base < cnt; base += 32) {
            int i = base + lane;
            if (i < cnt) {
                int tw = __ldg(&g_alist[t * 512 + i]);
                float u = (tw == t - 1) ? uhv : g_uh[(size_t)tw * H_ + h];
                part += sigf(r1v + u);
            }
        }
        float rs = warpsum(part) + (float)(N_ - cnt) * sigf(r1v);

        float sv = 0.f;
        if (act && lane == 0) {
            float sa = g_Sact[a * H_ + h];                    // column h owned by this thread
            sv = sa - (sub >= 0 ? g_hedge[(size_t)sub * H_ + h] : 0.f);
            g_snap[(size_t)t * H_ + h] = sa;
            g_sbuf[h] = sv;
            g_rbuf[h] = rs;
        }
        gridbar(++gen);

        // ---- Phase B: z/gated matvecs, new_h, state updates ----
        float az = 0.f, ag = 0.f;
#pragma unroll
        for (int s = 0; s < 15; s++) {
            int k = s * 32 + lane;
            az += wz[s] * __ldcg(&g_sbuf[k]);
            ag += wh[s] * __ldcg(&g_rbuf[k]);
        }
        az = warpsum(az);
        ag = warpsum(ag);
        if (act && lane == 0) {
            float z  = sigf(az + g_zpre[a * H_ + h]);
            float gg = tanhf(ag + g_wpre[a * H_ + h]);
            float nh = (1.f - z) * sv + z * gg;
            g_hedge[(size_t)t * H_ + h] = nh;
            if (t < L_ - 1) g_Sact[bn * H_ + h] += nh;        // single writer per (bn,h)
        }
        gridbar(++gen);
    }
}

// ---------------- epilogue: pred_stops (batched d3 GEMM) + trivial copies (R1-identical) ----------------
#define TT 8
__global__ __launch_bounds__(256) void k_dstop(
    const float* __restrict__ Wd3_w, const float* __restrict__ Wd3_b,
    const float* __restrict__ Ud_w, const float* __restrict__ Ud_b,
    const int* __restrict__ node_ids, const int* __restrict__ stops_in,
    const int* __restrict__ real_labels, float* __restrict__ out) {
    __shared__ float s_snap[TT][H_];
    __shared__ float s_acc[TT];
    int tid = threadIdx.x, wid = tid >> 5, lane = tid & 31;
    int t0 = blockIdx.x * TT;
    for (int i = tid; i < TT * H_; i += 256) {
        int tt = i / H_, hh = i - tt * H_;
        int t = t0 + tt;
        s_snap[tt][hh] = (t < L_) ? g_snap[(size_t)t * H_ + hh] : 0.f;
    }
    if (tid < TT) s_acc[tid] = 0.f;
    __syncthreads();
    for (int hh = wid; hh < H_; hh += 8) {
        float acc[TT];
#pragma unroll
        for (int i = 0; i < TT; i++) acc[i] = 0.f;
        for (int k = lane; k < H_; k += 32) {
            float w = Wd3_w[(size_t)hh * H_ + k];
#pragma unroll
            for (int i = 0; i < TT; i++) acc[i] += w * s_snap[i][k];
        }
#pragma unroll
        for (int i = 0; i < TT; i++) acc[i] = warpsum(acc[i]);
        if (lane == 0) {
            float wb = Wd3_b[hh], uw = Ud_w[H_ + hh];
#pragma unroll
            for (int i = 0; i < TT; i++) {
                float d3 = acc[i] + wb;
                if (d3 > 0.f) atomicAdd(&s_acc[i], uw * d3);
            }
        }
    }
    __syncthreads();
    if (tid < TT) {
        int t = t0 + tid;
        if (t < L_) {
            out[O_PSTOP + t] = g_c1[node_ids[t]] + s_acc[tid] + Ud_b[0];
            out[t] = (float)stops_in[t];
        }
    }
    if (blockIdx.x == 0 && tid < N_) out[O_RLAB + tid] = (float)real_labels[tid];
}

// ---------------- epilogue: labels (R1-identical) ----------------
__global__ __launch_bounds__(256) void k_labels(
    const float* __restrict__ Wl_w, const float* __restrict__ Ul_w,
    const float* __restrict__ Ul_b, const int* __restrict__ label_steps,
    float* __restrict__ out) {
    __shared__ float s_t1[H_];
    __shared__ float s_lg[V_];
    __shared__ float s_red[8];
    int tid = threadIdx.x, wid = tid >> 5, lane = tid & 31;
    for (int ii = 0; ii < 4; ii++) {
        int item = blockIdx.x * 4 + ii;
        if (item >= NLAB_) break;
        bool root = (item == 0);
        const float* x = root ? (const float*)0
                              : &g_hedge[(size_t)__ldg(&label_steps[item - 1]) * H_];
        for (int hh = wid; hh < H_; hh += 8) {
            float acc = 0.f;
            if (!root) {
                const float* wr = &Wl_w[(size_t)hh * (H_ + LAT_) + LAT_];
                for (int k = lane; k < H_; k += 32) acc += wr[k] * x[k];
            }
            acc = warpsum(acc);
            if (lane == 0) {
                float vv = g_wllat[hh] + acc;
                s_t1[hh] = root ? vv : fmaxf(vv, 0.f);   // root: NO relu on hidden
            }
        }
        __syncthreads();
        for (int v = wid; v < V_; v += 8) {
            float acc = 0.f;
            const float* urow = &Ul_w[(size_t)v * H_];
            for (int k = lane; k < H_; k += 32) acc += urow[k] * s_t1[k];
            acc = warpsum(acc);
            if (lane == 0) s_lg[v] = acc + Ul_b[v];
        }
        __syncthreads();
        float* orow = &out[O_PLAB + (size_t)item * V_];
        if (root) {
            // root label: relu(logits), no softmax
            for (int v = tid; v < V_; v += 256) orow[v] = fmaxf(s_lg[v], 0.f);
        } else {
            float m = -1e30f;
            for (int v = tid; v < V_; v += 256) m = fmaxf(m, s_lg[v]);
#pragma unroll
            for (int o = 16; o; o >>= 1) m = fmaxf(m, __shfl_xor_sync(0xffffffffu, m, o));
            if (lane == 0) s_red[wid] = m;
            __syncthreads();
            m = s_red[0];
#pragma unroll
            for (int w = 1; w < 8; w++) m = fmaxf(m, s_red[w]);
            __syncthreads();                      // protect s_red before reuse
            float ssum = 0.f;
            for (int v = tid; v < V_; v += 256) ssum += __expf(s_lg[v] - m);
            ssum = warpsum(ssum);
            if (lane == 0) s_red[wid] = ssum;
            __syncthreads();
            float tot = 0.f;
#pragma unroll
            for (int w = 0; w < 8; w++) tot += s_red[w];
            float inv = 1.f / tot;
            for (int v = tid; v < V_; v += 256) orow[v] = __expf(s_lg[v] - m) * inv;
        }
        __syncthreads();
    }
}

// ---------------- launch ----------------
extern "C" void kernel_launch(void* const* d_in, const int* in_sizes, int n_in,
                              void* d_out, int out_size) {
    const float* latent      = (const float*)d_in[0];
    const float* nf          = (const float*)d_in[1];
    const int*   node_ids    = (const int*)d_in[2];
    const int*   next_ids    = (const int*)d_in[3];
    const int*   stops       = (const int*)d_in[4];
    const int*   label_steps = (const int*)d_in[5];
    const int*   real_labels = (const int*)d_in[6];
    const float* Wz_w  = (const float*)d_in[7];
    const float* Wz_b  = (const float*)d_in[8];
    const float* Ur_w  = (const float*)d_in[9];
    const float* Wr_w  = (const float*)d_in[10];
    const float* Wr_b  = (const float*)d_in[11];
    const float* Wh_w  = (const float*)d_in[12];
    const float* Wh_b  = (const float*)d_in[13];
    const float* Wd12_w = (const float*)d_in[14];
    const float* Wd12_b = (const float*)d_in[15];
    const float* Wd3_w  = (const float*)d_in[16];
    const float* Wd3_b  = (const float*)d_in[17];
    const float* Ud_w   = (const float*)d_in[18];
    const float* Ud_b   = (const float*)d_in[19];
    const float* Wl_w   = (const float*)d_in[20];
    const float* Wl_b   = (const float*)d_in[21];
    const float* Ul_w   = (const float*)d_in[22];
    const float* Ul_b   = (const float*)d_in[23];
    float* out = (float*)d_out;

    k_zero<<<64, 256>>>();
    k_tables<<<N_, 256>>>(nf, latent, Wz_w, Wz_b, Wr_w, Wr_b, Wh_w, Wh_b,
                          Wd12_w, Wd12_b, Ud_w, Wl_w, Wl_b);
    k_path<<<(L_ + 127) / 128, 128>>>(node_ids, next_ids);
    k_seq<<<NB, NT>>>(node_ids, next_ids, Wz_w, Wh_w, Ur_w);
    k_dstop<<<(L_ + TT - 1) / TT, 256>>>(Wd3_w, Wd3_b, Ud_w, Ud_b, node_ids, stops,
                                         real_labels, out);
    k_labels<<<(NLAB_ + 3) / 4, 256>>>(Wl_w, Ul_w, Ul_b, label_steps, out);
}

// round 15
// speedup vs baseline: 1.8495x; 1.8495x over previous
#include <cuda_runtime.h>

#define N_    256
#define H_    450
#define LAT_  56
#define V_    780
#define L_    511
#define NLAB_ 256
#define WZLD  (V_ + H_)

#define NB 15          // persistent blocks
#define NT 512         // threads per block (16 warps)

#define O_PSTOP 511
#define O_RLAB  1022
#define O_PLAB  1278

// ---------------- static device scratch ----------------
__device__ float  g_hedge[L_ * H_];    // h written at step t (edge a_t -> b_t)
__device__ float2 g_srbuf[512];        // per-step (s, rsum) exchange (barrier-protected)
__device__ float  g_uhT[H_ * 512];     // [h][t] = Ur_h . h_edge[t]   (warp-private rows)
__device__ float  g_snap[L_ * H_];     // Sact[a_t] snapshot for d3 GEMM
__device__ float  g_zpre[N_ * H_];
__device__ float  g_wpre[N_ * H_];
__device__ float  g_r1[N_ * H_];
__device__ float  g_c1[N_];
__device__ float  g_wllat[H_];         // Wl[:, :LAT]@latent + Wl_b
__device__ float  g_d12lat[H_];        // Wd12[:, V:]@latent + Wd12_b
__device__ int    g_alist[L_ * 512];   // active in-edge steps (excluding t-1 and sub)
__device__ int    g_acnt[L_];
__device__ int    g_asub[L_];
__device__ int    g_prevact[L_];       // 1 if edge written at t-1 is active (not the sub edge)
__device__ int    g_flags[32];

__device__ __forceinline__ float sigf(float x) { return 1.0f / (1.0f + __expf(-x)); }

__device__ __forceinline__ float warpsum(float v) {
#pragma unroll
    for (int o = 16; o; o >>= 1) v += __shfl_xor_sync(0xffffffffu, v, o);
    return v;
}

// ---------------- setup kernels (proven) ----------------
__global__ void k_zero() {
    if (threadIdx.x < 32) g_flags[threadIdx.x] = 0;
}

__global__ __launch_bounds__(256) void k_lat(
    const float* __restrict__ latent,
    const float* __restrict__ Wd12_w, const float* __restrict__ Wd12_b,
    const float* __restrict__ Wl_w, const float* __restrict__ Wl_b) {
    int h = blockIdx.x * 256 + threadIdx.x;
    if (h >= H_) return;
    float d = Wd12_b[h];
    for (int l = 0; l < LAT_; l++)
        d += Wd12_w[(size_t)h * (V_ + LAT_) + V_ + l] * latent[l];
    g_d12lat[h] = d;
    float w = Wl_b[h];
    for (int l = 0; l < LAT_; l++)
        w += Wl_w[(size_t)h * (H_ + LAT_) + l] * latent[l];
    g_wllat[h] = w;
}

__global__ __launch_bounds__(256) void k_tables(
    const float* __restrict__ nf,
    const float* __restrict__ Wz_w, const float* __restrict__ Wz_b,
    const float* __restrict__ Wr_w, const float* __restrict__ Wr_b,
    const float* __restrict__ Wh_w, const float* __restrict__ Wh_b,
    const float* __restrict__ Wd12_w, const float* __restrict__ Ud_w) {
    __shared__ int   s_vid;
    __shared__ float s_red[256];
    int n = blockIdx.x, tid = threadIdx.x;
    if (tid == 0) s_vid = 0;
    __syncthreads();
    for (int j = tid; j < V_; j += 256)
        if (nf[(size_t)n * V_ + j] > 0.5f) s_vid = j;   // one-hot: exactly one writer
    __syncthreads();
    int v = s_vid;
    float part = 0.f;
    for (int h = tid; h < H_; h += 256) {
        g_zpre[n * H_ + h] = Wz_w[(size_t)h * WZLD + v] + Wz_b[h];
        g_wpre[n * H_ + h] = Wh_w[(size_t)h * WZLD + v] + Wh_b[h];
        g_r1[n * H_ + h]   = Wr_w[(size_t)h * V_ + v] + Wr_b[h];
        float d = g_d12lat[h] + Wd12_w[(size_t)h * (V_ + LAT_) + v];
        part += Ud_w[h] * fmaxf(d, 0.f);
    }
    s_red[tid] = part;
    __syncthreads();
    for (int s = 128; s; s >>= 1) { if (tid < s) s_red[tid] += s_red[tid + s]; __syncthreads(); }
    if (tid == 0) g_c1[n] = s_red[0];
}

__global__ void k_path(const int* __restrict__ a_, const int* __restrict__ b_) {
    int t = blockIdx.x * blockDim.x + threadIdx.x;
    if (t >= L_) return;
    int a = a_[t], b = b_[t];
    int cnt = 0, sub = -1, pact = 0;
    for (int tw = 0; tw < t; tw++) {
        if (b_[tw] == a) {
            if (a_[tw] == b) sub = tw;
            else if (tw == t - 1) pact = 1;
            else g_alist[t * 512 + cnt++] = tw;
        }
    }
    g_acnt[t] = cnt;
    g_asub[t] = sub;
    g_prevact[t] = pact;
}

// ---------------- flag-based grid barrier (release/acquire, proven green) ----------------
__device__ __forceinline__ void stflag(int bid, int gen) {
    asm volatile("st.release.gpu.global.b32 [%0], %1;" :: "l"(&g_flags[bid]), "r"(gen) : "memory");
}
__device__ __forceinline__ int ldflag(int i) {
    int v;
    asm volatile("ld.acquire.gpu.global.b32 %0, [%1];" : "=r"(v) : "l"(&g_flags[i]) : "memory");
    return v;
}
__device__ __forceinline__ void gridbar(int gen) {
    __syncthreads();
    if (threadIdx.x < 32) {
        if (threadIdx.x == 0) stflag(blockIdx.x, gen);
        bool done = threadIdx.x >= NB;
        for (;;) {
            if (__all_sync(0xffffffffu, done)) break;
            if (!done) done = ldflag(threadIdx.x) >= gen;
        }
    }
    __syncthreads();
}

// ---------------- the sequential recurrence: green-2872 protocol, 2 rows/warp ----------------
__global__ void __launch_bounds__(NT, 1) k_seq(
    const int* __restrict__ node_ids, const int* __restrict__ next_ids,
    const float* __restrict__ Wz_w, const float* __restrict__ Wh_w,
    const float* __restrict__ Ur_w) {
    __shared__ float sh_h[512];
    __shared__ float sh_s[512];
    __shared__ float sh_r[512];
    int tid = threadIdx.x, lane = tid & 31, wid = tid >> 5;
    int gw = blockIdx.x * 16 + wid;           // 0..239
    int hA = gw;                              // always active (<240 < 450)
    int hB = gw + 240;                        // active if < 450
    bool actB = hB < H_;
    int hBc = actB ? hB : H_ - 1;

    // zero pad slots once (never rewritten; staging loops only touch tid<H_)
    if (tid >= H_) { sh_h[tid] = 0.f; sh_s[tid] = 0.f; sh_r[tid] = 0.f; }
    __syncthreads();

    // weight rows in registers (zero-padded)
    float urA[15], wzA[15], whA[15], urB[15], wzB[15], whB[15];
#pragma unroll
    for (int s = 0; s < 15; s++) {
        int k = s * 32 + lane;
        bool ok = k < H_;
        urA[s] = ok ? Ur_w[(size_t)hA * H_ + k] : 0.f;
        wzA[s] = ok ? Wz_w[(size_t)hA * WZLD + V_ + k] : 0.f;
        whA[s] = ok ? Wh_w[(size_t)hA * WZLD + V_ + k] : 0.f;
        bool okB = ok && actB;
        urB[s] = okB ? Ur_w[(size_t)hB * H_ + k] : 0.f;
        wzB[s] = okB ? Wz_w[(size_t)hB * WZLD + V_ + k] : 0.f;
        whB[s] = okB ? Wh_w[(size_t)hB * WZLD + V_ + k] : 0.f;
    }
    // Sact[v][row] in registers: lane (v&31), slot (v>>5)
    float SarrA[8], SarrB[8];
#pragma unroll
    for (int i = 0; i < 8; i++) { SarrA[i] = 0.f; SarrB[i] = 0.f; }

    int gen = 0;
    for (int t = 0; t < L_; t++) {
        int a    = __ldg(&node_ids[t]);
        int bn   = __ldg(&next_ids[t]);
        int sub  = __ldg(&g_asub[t]);
        int cnt  = __ldg(&g_acnt[t]);
        int pact = __ldg(&g_prevact[t]);

        // ---- Phase A ----
        float hstage = 0.f;
        if (t > 0 && tid < H_) hstage = __ldcg(&g_hedge[(size_t)(t - 1) * H_ + tid]);
        float hsA = (sub >= 0) ? __ldcg(&g_hedge[(size_t)sub * H_ + hA])  : 0.f;
        float hsB = (sub >= 0) ? __ldcg(&g_hedge[(size_t)sub * H_ + hBc]) : 0.f;
        float r1vA = __ldg(&g_r1[a * H_ + hA]);
        float r1vB = __ldg(&g_r1[a * H_ + hBc]);
        // lane-parallel rsum over old active edges (t-1 handled via pact/uhv)
        float partA = 0.f, partB = 0.f;
        for (int base = 0; base < cnt; base += 32) {
            int i = base + lane;
            if (i < cnt) {
                int tw = __ldg(&g_alist[t * 512 + i]);
                partA += sigf(r1vA + g_uhT[(size_t)hA * 512 + tw]);
                partB += sigf(r1vB + g_uhT[(size_t)hBc * 512 + tw]);
            }
        }
        // Sact[a][row] lookups from registers
        int slot = a >> 5;
        float cA = SarrA[0], cB = SarrB[0];
#pragma unroll
        for (int i = 1; i < 8; i++) { cA = (slot == i) ? SarrA[i] : cA; cB = (slot == i) ? SarrB[i] : cB; }
        float saA = __shfl_sync(0xffffffffu, cA, a & 31);
        float saB = __shfl_sync(0xffffffffu, cB, a & 31);

        if (tid < H_) sh_h[tid] = hstage;
        __syncthreads();

        float uhvA = 0.f, uhvB = 0.f;
        if (t > 0) {
            float accA = 0.f, accB = 0.f;
#pragma unroll
            for (int s = 0; s < 15; s++) {
                float hv = sh_h[s * 32 + lane];
                accA += urA[s] * hv;
                accB += urB[s] * hv;
            }
            uhvA = warpsum(accA);
            uhvB = warpsum(accB);
            if (lane == 0) {
                g_uhT[(size_t)hA * 512 + (t - 1)] = uhvA;
                if (actB) g_uhT[(size_t)hB * 512 + (t - 1)] = uhvB;
            }
        }
        float rsA = warpsum(partA) + (float)(N_ - cnt - pact) * sigf(r1vA);
        float rsB = warpsum(partB) + (float)(N_ - cnt - pact) * sigf(r1vB);
        if (pact) { rsA += sigf(r1vA + uhvA); rsB += sigf(r1vB + uhvB); }
        float svA = saA - hsA;
        float svB = saB - hsB;
        if (lane == 0) {
            __stcg(&g_srbuf[hA], make_float2(svA, rsA));    // vectorized (s, rsum) publish
            g_snap[(size_t)t * H_ + hA] = saA;
            if (actB) {
                __stcg(&g_srbuf[hB], make_float2(svB, rsB));
                g_snap[(size_t)t * H_ + hB] = saB;
            }
        }
        gridbar(++gen);

        // ---- Phase B ----
        if (tid < H_) {
            float2 sr = __ldcg(&g_srbuf[tid]);
            sh_s[tid] = sr.x;
            sh_r[tid] = sr.y;
        }
        __syncthreads();

        float azA = 0.f, agA = 0.f, azB = 0.f, agB = 0.f;
#pragma unroll
        for (int s = 0; s < 15; s++) {
            float sv1 = sh_s[s * 32 + lane];
            float rv1 = sh_r[s * 32 + lane];
            azA += wzA[s] * sv1;
            agA += whA[s] * rv1;
            azB += wzB[s] * sv1;
            agB += whB[s] * rv1;
        }
        azA = warpsum(azA);
        agA = warpsum(agA);
        azB = warpsum(azB);
        agB = warpsum(agB);
        float zA  = sigf(azA + __ldg(&g_zpre[a * H_ + hA]));
        float ggA = tanhf(agA + __ldg(&g_wpre[a * H_ + hA]));
        float nhA = (1.f - zA) * svA + zA * ggA;
        float zB  = sigf(azB + __ldg(&g_zpre[a * H_ + hBc]));
        float ggB = tanhf(agB + __ldg(&g_wpre[a * H_ + hBc]));
        float nhB = (1.f - zB) * svB + zB * ggB;
        if (lane == 0) {
            __stcg(&g_hedge[(size_t)t * H_ + hA], nhA);
            if (actB) __stcg(&g_hedge[(size_t)t * H_ + hB], nhB);
        }
        if (t < L_ - 1 && lane == (bn & 31)) {
            int bs = bn >> 5;
#pragma unroll
            for (int i = 0; i < 8; i++) {
                if (bs == i) { SarrA[i] += nhA; if (actB) SarrB[i] += nhB; }
            }
        }
        if (t < L_ - 1) gridbar(++gen);   // final flush handled by kernel boundary
    }
}

// ---------------- epilogue: pred_stops + copies (proven) ----------------
#define TT 16
__global__ __launch_bounds__(256) void k_dstop(
    const float* __restrict__ Wd3_w, const float* __restrict__ Wd3_b,
    const float* __restrict__ Ud_w, const float* __restrict__ Ud_b,
    const int* __restrict__ node_ids, const int* __restrict__ stops_in,
    const int* __restrict__ real_labels, float* __restrict__ out) {
    __shared__ float s_snap[TT][H_];
    __shared__ float s_acc[TT];
    int tid = threadIdx.x, wid = tid >> 5, lane = tid & 31;
    int t0 = blockIdx.x * TT;
    for (int i = tid; i < TT * H_; i += 256) {
        int tt = i / H_, hh = i - tt * H_;
        int t = t0 + tt;
        s_snap[tt][hh] = (t < L_) ? g_snap[(size_t)t * H_ + hh] : 0.f;
    }
    if (tid < TT) s_acc[tid] = 0.f;
    __syncthreads();
    for (int hh = wid; hh < H_; hh += 8) {
        float acc[TT];
#pragma unroll
        for (int i = 0; i < TT; i++) acc[i] = 0.f;
        for (int k = lane; k < H_; k += 32) {
            float w = Wd3_w[(size_t)hh * H_ + k];
#pragma unroll
            for (int i = 0; i < TT; i++) acc[i] += w * s_snap[i][k];
        }
#pragma unroll
        for (int i = 0; i < TT; i++) acc[i] = warpsum(acc[i]);
        if (lane == 0) {
            float wb = Wd3_b[hh], uw = Ud_w[H_ + hh];
#pragma unroll
            for (int i = 0; i < TT; i++) {
                float d3 = acc[i] + wb;
                if (d3 > 0.f) atomicAdd(&s_acc[i], uw * d3);
            }
        }
    }
    __syncthreads();
    if (tid < TT) {
        int t = t0 + tid;
        if (t < L_) {
            out[O_PSTOP + t] = g_c1[node_ids[t]] + s_acc[tid] + Ud_b[0];
            out[t] = (float)stops_in[t];
        }
    }
    if (blockIdx.x == 0 && tid < N_) out[O_RLAB + tid] = (float)real_labels[tid];
}

// ---------------- epilogue: labels (8 items per block, proven) ----------------
#define LIT 8
__global__ __launch_bounds__(256) void k_labels(
    const float* __restrict__ Wl_w, const float* __restrict__ Ul_w,
    const float* __restrict__ Ul_b, const int* __restrict__ label_steps,
    float* __restrict__ out) {
    __shared__ float s_x[LIT][452];
    __shared__ float s_t1[LIT][452];
    int tid = threadIdx.x, wid = tid >> 5, lane = tid & 31;
    int item0 = blockIdx.x * LIT;
    // stage hidden vectors (item 0 = root: zeros)
    for (int i = tid; i < LIT * H_; i += 256) {
        int ii = i / H_, k = i - ii * H_;
        int item = item0 + ii;
        float v = 0.f;
        if (item > 0) v = g_hedge[(size_t)__ldg(&label_steps[item - 1]) * H_ + k];
        s_x[ii][k] = v;
    }
    __syncthreads();
    // t1 = relu(Wl_h . x + wllat)   (root: wllat, NO relu)
    for (int hh = wid; hh < H_; hh += 8) {
        float acc[LIT];
#pragma unroll
        for (int ii = 0; ii < LIT; ii++) acc[ii] = 0.f;
        for (int k = lane; k < H_; k += 32) {
            float w = Wl_w[(size_t)hh * (H_ + LAT_) + LAT_ + k];
#pragma unroll
            for (int ii = 0; ii < LIT; ii++) acc[ii] += w * s_x[ii][k];
        }
#pragma unroll
        for (int ii = 0; ii < LIT; ii++) acc[ii] = warpsum(acc[ii]);
        if (lane == 0) {
            float base = g_wllat[hh];
#pragma unroll
            for (int ii = 0; ii < LIT; ii++) {
                bool root = (item0 + ii == 0);
                s_t1[ii][hh] = root ? base : fmaxf(base + acc[ii], 0.f);
            }
        }
    }
    __syncthreads();
    // logits -> out (then softmax in place)
    for (int v = wid; v < V_; v += 8) {
        float acc[LIT];
#pragma unroll
        for (int ii = 0; ii < LIT; ii++) acc[ii] = 0.f;
        for (int k = lane; k < H_; k += 32) {
            float u = Ul_w[(size_t)v * H_ + k];
#pragma unroll
            for (int ii = 0; ii < LIT; ii++) acc[ii] += u * s_t1[ii][k];
        }
#pragma unroll
        for (int ii = 0; ii < LIT; ii++) acc[ii] = warpsum(acc[ii]);
        if (lane == 0) {
            float b = Ul_b[v];
#pragma unroll
            for (int ii = 0; ii < LIT; ii++)
                out[O_PLAB + (size_t)(item0 + ii) * V_ + v] = acc[ii] + b;
        }
    }
    __syncthreads();
    // per-item softmax (warp ii owns item ii); root: relu only
    if (wid < LIT) {
        int item = item0 + wid;
        float* row = &out[O_PLAB + (size_t)item * V_];
        if (item == 0) {
            for (int v = lane; v < V_; v += 32) row[v] = fmaxf(row[v], 0.f);
        } else {
            float m = -1e30f;
            for (int v = lane; v < V_; v += 32) m = fmaxf(m, row[v]);
#pragma unroll
            for (int o = 16; o; o >>= 1) m = fmaxf(m, __shfl_xor_sync(0xffffffffu, m, o));
            float ssum = 0.f;
            for (int v = lane; v < V_; v += 32) ssum += __expf(row[v] - m);
            ssum = warpsum(ssum);
            float inv = 1.f / ssum;
            for (int v = lane; v < V_; v += 32) row[v] = __expf(row[v] - m) * inv;
        }
    }
}

// ---------------- launch ----------------
extern "C" void kernel_launch(void* const* d_in, const int* in_sizes, int n_in,
                              void* d_out, int out_size) {
    const float* latent      = (const float*)d_in[0];
    const float* nf          = (const float*)d_in[1];
    const int*   node_ids    = (const int*)d_in[2];
    const int*   next_ids    = (const int*)d_in[3];
    const int*   stops       = (const int*)d_in[4];
    const int*   label_steps = (const int*)d_in[5];
    const int*   real_labels = (const int*)d_in[6];
    const float* Wz_w  = (const float*)d_in[7];
    const float* Wz_b  = (const float*)d_in[8];
    const float* Ur_w  = (const float*)d_in[9];
    const float* Wr_w  = (const float*)d_in[10];
    const float* Wr_b  = (const float*)d_in[11];
    const float* Wh_w  = (const float*)d_in[12];
    const float* Wh_b  = (const float*)d_in[13];
    const float* Wd12_w = (const float*)d_in[14];
    const float* Wd12_b = (const float*)d_in[15];
    const float* Wd3_w  = (const float*)d_in[16];
    const float* Wd3_b  = (const float*)d_in[17];
    const float* Ud_w   = (const float*)d_in[18];
    const float* Ud_b   = (const float*)d_in[19];
    const float* Wl_w   = (const float*)d_in[20];
    const float* Wl_b   = (const float*)d_in[21];
    const float* Ul_w   = (const float*)d_in[22];
    const float* Ul_b   = (const float*)d_in[23];
    float* out = (float*)d_out;

    k_zero<<<1, 32>>>();
    k_lat<<<2, 256>>>(latent, Wd12_w, Wd12_b, Wl_w, Wl_b);
    k_tables<<<N_, 256>>>(nf, Wz_w, Wz_b, Wr_w, Wr_b, Wh_w, Wh_b, Wd12_w, Ud_w);
    k_path<<<(L_ + 127) / 128, 128>>>(node_ids, next_ids);
    k_seq<<<NB, NT>>>(node_ids, next_ids, Wz_w, Wh_w, Ur_w);
    k_dstop<<<(L_ + TT - 1) / TT, 256>>>(Wd3_w, Wd3_b, Ud_w, Ud_b, node_ids, stops,
                                         real_labels, out);
    k_labels<<<NLAB_ / LIT, 256>>>(Wl_w, Ul_w, Ul_b, label_steps, out);
}

// round 16
// speedup vs baseline: 2.1443x; 1.1593x over previous
#include <cuda_runtime.h>

#define N_    256
#define H_    450
#define LAT_  56
#define V_    780
#define L_    511
#define NLAB_ 256
#define WZLD  (V_ + H_)

#define NB 29          // persistent blocks
#define NT 512         // threads per block (16 warps)

#define O_PSTOP 511
#define O_RLAB  1022
#define O_PLAB  1278

// ---------------- static device scratch ----------------
__device__ float  g_hedge[L_ * H_];    // h written at step t (edge a_t -> b_t)
__device__ float2 g_srbuf[512];        // per-step (s, rsum) exchange (barrier-protected)
__device__ float  g_uhT[H_ * 512];     // [h][t] = Ur_h . h_edge[t]   (warp-private rows)
__device__ float  g_snap[L_ * H_];     // Sact[a_t] snapshot for d3 GEMM
__device__ float  g_zpre[N_ * H_];
__device__ float  g_wpre[N_ * H_];
__device__ float  g_r1[N_ * H_];
__device__ float  g_c1[N_];
__device__ float  g_wllat[H_];         // Wl[:, :LAT]@latent + Wl_b
__device__ float  g_d12lat[H_];        // Wd12[:, V:]@latent + Wd12_b
__device__ int    g_alist[L_ * 512];   // active in-edge steps (excluding t-1 and sub)
__device__ int    g_acnt[L_];
__device__ int    g_asub[L_];
__device__ int    g_prevact[L_];       // 1 if edge written at t-1 is active (not the sub edge)
__device__ int    g_flags[32];

__device__ __forceinline__ float sigf(float x) { return 1.0f / (1.0f + __expf(-x)); }

__device__ __forceinline__ float warpsum(float v) {
#pragma unroll
    for (int o = 16; o; o >>= 1) v += __shfl_xor_sync(0xffffffffu, v, o);
    return v;
}

// ---------------- setup kernels (proven) ----------------
__global__ void k_zero() {
    if (threadIdx.x < 32) g_flags[threadIdx.x] = 0;
}

__global__ __launch_bounds__(256) void k_lat(
    const float* __restrict__ latent,
    const float* __restrict__ Wd12_w, const float* __restrict__ Wd12_b,
    const float* __restrict__ Wl_w, const float* __restrict__ Wl_b) {
    int h = blockIdx.x * 256 + threadIdx.x;
    if (h >= H_) return;
    float d = Wd12_b[h];
    for (int l = 0; l < LAT_; l++)
        d += Wd12_w[(size_t)h * (V_ + LAT_) + V_ + l] * latent[l];
    g_d12lat[h] = d;
    float w = Wl_b[h];
    for (int l = 0; l < LAT_; l++)
        w += Wl_w[(size_t)h * (H_ + LAT_) + l] * latent[l];
    g_wllat[h] = w;
}

__global__ __launch_bounds__(256) void k_tables(
    const float* __restrict__ nf,
    const float* __restrict__ Wz_w, const float* __restrict__ Wz_b,
    const float* __restrict__ Wr_w, const float* __restrict__ Wr_b,
    const float* __restrict__ Wh_w, const float* __restrict__ Wh_b,
    const float* __restrict__ Wd12_w, const float* __restrict__ Ud_w) {
    __shared__ int   s_vid;
    __shared__ float s_red[256];
    int n = blockIdx.x, tid = threadIdx.x;
    if (tid == 0) s_vid = 0;
    __syncthreads();
    for (int j = tid; j < V_; j += 256)
        if (nf[(size_t)n * V_ + j] > 0.5f) s_vid = j;   // one-hot: exactly one writer
    __syncthreads();
    int v = s_vid;
    float part = 0.f;
    for (int h = tid; h < H_; h += 256) {
        g_zpre[n * H_ + h] = Wz_w[(size_t)h * WZLD + v] + Wz_b[h];
        g_wpre[n * H_ + h] = Wh_w[(size_t)h * WZLD + v] + Wh_b[h];
        g_r1[n * H_ + h]   = Wr_w[(size_t)h * V_ + v] + Wr_b[h];
        float d = g_d12lat[h] + Wd12_w[(size_t)h * (V_ + LAT_) + v];
        part += Ud_w[h] * fmaxf(d, 0.f);
    }
    s_red[tid] = part;
    __syncthreads();
    for (int s = 128; s; s >>= 1) { if (tid < s) s_red[tid] += s_red[tid + s]; __syncthreads(); }
    if (tid == 0) g_c1[n] = s_red[0];
}

__global__ void k_path(const int* __restrict__ a_, const int* __restrict__ b_) {
    int t = blockIdx.x * blockDim.x + threadIdx.x;
    if (t >= L_) return;
    int a = a_[t], b = b_[t];
    int cnt = 0, sub = -1, pact = 0;
    for (int tw = 0; tw < t; tw++) {
        if (b_[tw] == a) {
            if (a_[tw] == b) sub = tw;
            else if (tw == t - 1) pact = 1;
            else g_alist[t * 512 + cnt++] = tw;
        }
    }
    g_acnt[t] = cnt;
    g_asub[t] = sub;
    g_prevact[t] = pact;
}

// ---------------- flag-based grid barrier (release/acquire, proven green) ----------------
__device__ __forceinline__ void stflag(int bid, int gen) {
    asm volatile("st.release.gpu.global.b32 [%0], %1;" :: "l"(&g_flags[bid]), "r"(gen) : "memory");
}
__device__ __forceinline__ int ldflag(int i) {
    int v;
    asm volatile("ld.acquire.gpu.global.b32 %0, [%1];" : "=r"(v) : "l"(&g_flags[i]) : "memory");
    return v;
}
__device__ __forceinline__ void gridbar(int gen) {
    __syncthreads();
    if (threadIdx.x < 32) {
        if (threadIdx.x == 0) stflag(blockIdx.x, gen);
        bool done = threadIdx.x >= NB;
        for (;;) {
            if (__all_sync(0xffffffffu, done)) break;
            if (!done) done = ldflag(threadIdx.x) >= gen;
        }
    }
    __syncthreads();
}

// ---------------- the sequential recurrence: green-2873 protocol + software pipelining ----------------
// Phase A is minimal (stage hedge -> Ur matvec -> combine precomputed parts -> publish).
// Everything that only depends on data established before barrier-2 of step t
// (meta, r1, old-edge rsum gather, hs, Sact lookup) is computed in phase B of step t
// for step t+1. The leaf-return case sub==t uses the locally-computed nh directly.
__global__ void __launch_bounds__(NT, 1) k_seq(
    const int* __restrict__ node_ids, const int* __restrict__ next_ids,
    const float* __restrict__ Wz_w, const float* __restrict__ Wh_w,
    const float* __restrict__ Ur_w) {
    __shared__ float sh_h[512];
    __shared__ float sh_s[512];
    __shared__ float sh_r[512];
    int tid = threadIdx.x, lane = tid & 31, wid = tid >> 5;
    int h = blockIdx.x * 16 + wid;            // 0..463
    bool act = h < H_;
    int hc = act ? h : H_ - 1;

    // zero pad slots once (staging loops only touch tid < H_)
    if (tid >= H_) { sh_h[tid] = 0.f; sh_s[tid] = 0.f; sh_r[tid] = 0.f; }
    __syncthreads();

    // weight rows in registers (zero-padded)
    float ur[15], wz[15], wh[15];
#pragma unroll
    for (int s = 0; s < 15; s++) {
        int k = s * 32 + lane;
        bool ok = act && k < H_;
        ur[s] = ok ? Ur_w[(size_t)h * H_ + k] : 0.f;
        wz[s] = ok ? Wz_w[(size_t)h * WZLD + V_ + k] : 0.f;
        wh[s] = ok ? Wh_w[(size_t)h * WZLD + V_ + k] : 0.f;
    }
    // Sact[v][h] in registers: lane (v&31), slot (v>>5)
    float Sarr[8];
#pragma unroll
    for (int i = 0; i < 8; i++) Sarr[i] = 0.f;

    // ---- prime carries for step 0 (cnt=0, sub=-1, pact=0 at t=0) ----
    int a    = __ldg(&node_ids[0]);
    int bn   = __ldg(&next_ids[0]);
    int cnt  = __ldg(&g_acnt[0]);
    int pact = __ldg(&g_prevact[0]);
    float r1v    = __ldg(&g_r1[a * H_ + hc]);
    float rs_old = 0.f;     // alist(0) empty
    float hs     = 0.f;     // sub(0) == -1
    float sa     = 0.f;     // Sact all-zero

    int gen = 0;
    for (int t = 0; t < L_; t++) {
        // ---- Phase A (minimal critical path) ----
        float hstage = 0.f;
        if (t > 0 && tid < H_) hstage = __ldcg(&g_hedge[(size_t)(t - 1) * H_ + tid]);
        if (tid < H_) sh_h[tid] = hstage;
        __syncthreads();

        float uhv = 0.f;
        if (t > 0) {
            float acc = 0.f;
#pragma unroll
            for (int s = 0; s < 15; s++) acc += ur[s] * sh_h[s * 32 + lane];
            uhv = warpsum(acc);
            if (act && lane == 0) g_uhT[(size_t)h * 512 + (t - 1)] = uhv;
        }
        float rs = rs_old + (float)(N_ - cnt - pact) * sigf(r1v);
        if (pact) rs += sigf(r1v + uhv);
        float sv = sa - hs;
        if (act && lane == 0)
            __stcg(&g_srbuf[h], make_float2(sv, rs));     // publish (s, rsum)
        gridbar(++gen);

        // ---- Phase B ----
        if (tid < H_) {
            float2 sr = __ldcg(&g_srbuf[tid]);
            sh_s[tid] = sr.x;
            sh_r[tid] = sr.y;
        }
        __syncthreads();

        float az = 0.f, ag = 0.f;
#pragma unroll
        for (int s = 0; s < 15; s++) {
            az += wz[s] * sh_s[s * 32 + lane];
            ag += wh[s] * sh_r[s * 32 + lane];
        }
        az = warpsum(az);
        ag = warpsum(ag);
        float z  = sigf(az + __ldg(&g_zpre[a * H_ + hc]));
        float gg = tanhf(ag + __ldg(&g_wpre[a * H_ + hc]));
        float nh = (1.f - z) * sv + z * gg;
        if (act && lane == 0) {
            __stcg(&g_hedge[(size_t)t * H_ + h], nh);     // publish new_h
            g_snap[(size_t)t * H_ + h] = sa;              // epilogue-only, off phase-A drain
        }
        if (act && t < L_ - 1 && lane == (bn & 31)) {
            int bs = bn >> 5;
#pragma unroll
            for (int i = 0; i < 8; i++) if (bs == i) Sarr[i] += nh;
        }

        if (t < L_ - 1) {
            // ---- pregather for step t+1 (everything established before barrier-2(t)) ----
            int a2    = bn;                      // node_ids[t+1] == next_ids[t] by construction
            int bn2   = __ldg(&next_ids[t + 1]);
            int sub2  = __ldg(&g_asub[t + 1]);
            int cnt2  = __ldg(&g_acnt[t + 1]);
            int pact2 = __ldg(&g_prevact[t + 1]);
            float r1v2 = __ldg(&g_r1[a2 * H_ + hc]);
            // old-edge rsum part: all tw <= t-1, uhT written by own warp by phase A(t)
            float part = 0.f;
            for (int base = 0; base < cnt2; base += 32) {
                int i = base + lane;
                if (i < cnt2) {
                    int tw = __ldg(&g_alist[(t + 1) * 512 + i]);
                    part += sigf(r1v2 + g_uhT[(size_t)hc * 512 + tw]);
                }
            }
            float rs_old2 = warpsum(part);
            // hs(t+1): sub2==t is the leaf-return case -> locally computed nh (no exchange!)
            float hs2;
            if (sub2 < 0)       hs2 = 0.f;
            else if (sub2 == t) hs2 = nh;
            else                hs2 = __ldcg(&g_hedge[(size_t)sub2 * H_ + hc]);
            // Sact[a2] lookup AFTER the Sarr update above (a2 == bn, includes nh)
            int slot = a2 >> 5;
            float c = Sarr[0];
#pragma unroll
            for (int i = 1; i < 8; i++) c = (slot == i) ? Sarr[i] : c;
            float sa2 = __shfl_sync(0xffffffffu, c, a2 & 31);
            // commit carries
            a = a2; bn = bn2; cnt = cnt2; pact = pact2;
            r1v = r1v2; rs_old = rs_old2; hs = hs2; sa = sa2;
            gridbar(++gen);      // final flush handled by kernel boundary on last step
        }
    }
}

// ---------------- epilogue: pred_stops + copies (proven) ----------------
#define TT 16
__global__ __launch_bounds__(256) void k_dstop(
    const float* __restrict__ Wd3_w, const float* __restrict__ Wd3_b,
    const float* __restrict__ Ud_w, const float* __restrict__ Ud_b,
    const int* __restrict__ node_ids, const int* __restrict__ stops_in,
    const int* __restrict__ real_labels, float* __restrict__ out) {
    __shared__ float s_snap[TT][H_];
    __shared__ float s_acc[TT];
    int tid = threadIdx.x, wid = tid >> 5, lane = tid & 31;
    int t0 = blockIdx.x * TT;
    for (int i = tid; i < TT * H_; i += 256) {
        int tt = i / H_, hh = i - tt * H_;
        int t = t0 + tt;
        s_snap[tt][hh] = (t < L_) ? g_snap[(size_t)t * H_ + hh] : 0.f;
    }
    if (tid < TT) s_acc[tid] = 0.f;
    __syncthreads();
    for (int hh = wid; hh < H_; hh += 8) {
        float acc[TT];
#pragma unroll
        for (int i = 0; i < TT; i++) acc[i] = 0.f;
        for (int k = lane; k < H_; k += 32) {
            float w = Wd3_w[(size_t)hh * H_ + k];
#pragma unroll
            for (int i = 0; i < TT; i++) acc[i] += w * s_snap[i][k];
        }
#pragma unroll
        for (int i = 0; i < TT; i++) acc[i] = warpsum(acc[i]);
        if (lane == 0) {
            float wb = Wd3_b[hh], uw = Ud_w[H_ + hh];
#pragma unroll
            for (int i = 0; i < TT; i++) {
                float d3 = acc[i] + wb;
                if (d3 > 0.f) atomicAdd(&s_acc[i], uw * d3);
            }
        }
    }
    __syncthreads();
    if (tid < TT) {
        int t = t0 + tid;
        if (t < L_) {
            out[O_PSTOP + t] = g_c1[node_ids[t]] + s_acc[tid] + Ud_b[0];
            out[t] = (float)stops_in[t];
        }
    }
    if (blockIdx.x == 0 && tid < N_) out[O_RLAB + tid] = (float)real_labels[tid];
}

// ---------------- epilogue: labels (8 items per block, proven) ----------------
#define LIT 8
__global__ __launch_bounds__(256) void k_labels(
    const float* __restrict__ Wl_w, const float* __restrict__ Ul_w,
    const float* __restrict__ Ul_b, const int* __restrict__ label_steps,
    float* __restrict__ out) {
    __shared__ float s_x[LIT][452];
    __shared__ float s_t1[LIT][452];
    int tid = threadIdx.x, wid = tid >> 5, lane = tid & 31;
    int item0 = blockIdx.x * LIT;
    // stage hidden vectors (item 0 = root: zeros)
    for (int i = tid; i < LIT * H_; i += 256) {
        int ii = i / H_, k = i - ii * H_;
        int item = item0 + ii;
        float v = 0.f;
        if (item > 0) v = g_hedge[(size_t)__ldg(&label_steps[item - 1]) * H_ + k];
        s_x[ii][k] = v;
    }
    __syncthreads();
    // t1 = relu(Wl_h . x + wllat)   (root: wllat, NO relu)
    for (int hh = wid; hh < H_; hh += 8) {
        float acc[LIT];
#pragma unroll
        for (int ii = 0; ii < LIT; ii++) acc[ii] = 0.f;
        for (int k = lane; k < H_; k += 32) {
            float w = Wl_w[(size_t)hh * (H_ + LAT_) + LAT_ + k];
#pragma unroll
            for (int ii = 0; ii < LIT; ii++) acc[ii] += w * s_x[ii][k];
        }
#pragma unroll
        for (int ii = 0; ii < LIT; ii++) acc[ii] = warpsum(acc[ii]);
        if (lane == 0) {
            float base = g_wllat[hh];
#pragma unroll
            for (int ii = 0; ii < LIT; ii++) {
                bool root = (item0 + ii == 0);
                s_t1[ii][hh] = root ? base : fmaxf(base + acc[ii], 0.f);
            }
        }
    }
    __syncthreads();
    // logits -> out (then softmax in place)
    for (int v = wid; v < V_; v += 8) {
        float acc[LIT];
#pragma unroll
        for (int ii = 0; ii < LIT; ii++) acc[ii] = 0.f;
        for (int k = lane; k < H_; k += 32) {
            float u = Ul_w[(size_t)v * H_ + k];
#pragma unroll
            for (int ii = 0; ii < LIT; ii++) acc[ii] += u * s_t1[ii][k];
        }
#pragma unroll
        for (int ii = 0; ii < LIT; ii++) acc[ii] = warpsum(acc[ii]);
        if (lane == 0) {
            float b = Ul_b[v];
#pragma unroll
            for (int ii = 0; ii < LIT; ii++)
                out[O_PLAB + (size_t)(item0 + ii) * V_ + v] = acc[ii] + b;
        }
    }
    __syncthreads();
    // per-item softmax (warp ii owns item ii); root: relu only
    if (wid < LIT) {
        int item = item0 + wid;
        float* row = &out[O_PLAB + (size_t)item * V_];
        if (item == 0) {
            for (int v = lane; v < V_; v += 32) row[v] = fmaxf(row[v], 0.f);
        } else {
            float m = -1e30f;
            for (int v = lane; v < V_; v += 32) m = fmaxf(m, row[v]);
#pragma unroll
            for (int o = 16; o; o >>= 1) m = fmaxf(m, __shfl_xor_sync(0xffffffffu, m, o));
            float ssum = 0.f;
            for (int v = lane; v < V_; v += 32) ssum += __expf(row[v] - m);
            ssum = warpsum(ssum);
            float inv = 1.f / ssum;
            for (int v = lane; v < V_; v += 32) row[v] = __expf(row[v] - m) * inv;
        }
    }
}

// ---------------- launch ----------------
extern "C" void kernel_launch(void* const* d_in, const int* in_sizes, int n_in,
                              void* d_out, int out_size) {
    const float* latent      = (const float*)d_in[0];
    const float* nf          = (const float*)d_in[1];
    const int*   node_ids    = (const int*)d_in[2];
    const int*   next_ids    = (const int*)d_in[3];
    const int*   stops       = (const int*)d_in[4];
    const int*   label_steps = (const int*)d_in[5];
    const int*   real_labels = (const int*)d_in[6];
    const float* Wz_w  = (const float*)d_in[7];
    const float* Wz_b  = (const float*)d_in[8];
    const float* Ur_w  = (const float*)d_in[9];
    const float* Wr_w  = (const float*)d_in[10];
    const float* Wr_b  = (const float*)d_in[11];
    const float* Wh_w  = (const float*)d_in[12];
    const float* Wh_b  = (const float*)d_in[13];
    const float* Wd12_w = (const float*)d_in[14];
    const float* Wd12_b = (const float*)d_in[15];
    const float* Wd3_w  = (const float*)d_in[16];
    const float* Wd3_b  = (const float*)d_in[17];
    const float* Ud_w   = (const float*)d_in[18];
    const float* Ud_b   = (const float*)d_in[19];
    const float* Wl_w   = (const float*)d_in[20];
    const float* Wl_b   = (const float*)d_in[21];
    const float* Ul_w   = (const float*)d_in[22];
    const float* Ul_b   = (const float*)d_in[23];
    float* out = (float*)d_out;

    k_zero<<<1, 32>>>();
    k_lat<<<2, 256>>>(latent, Wd12_w, Wd12_b, Wl_w, Wl_b);
    k_tables<<<N_, 256>>>(nf, Wz_w, Wz_b, Wr_w, Wr_b, Wh_w, Wh_b, Wd12_w, Ud_w);
    k_path<<<(L_ + 127) / 128, 128>>>(node_ids, next_ids);
    k_seq<<<NB, NT>>>(node_ids, next_ids, Wz_w, Wh_w, Ur_w);
    k_dstop<<<(L_ + TT - 1) / TT, 256>>>(Wd3_w, Wd3_b, Ud_w, Ud_b, node_ids, stops,
                                         real_labels, out);
    k_labels<<<NLAB_ / LIT, 256>>>(Wl_w, Ul_w, Ul_b, label_steps, out);
}